// round 11
// baseline (speedup 1.0000x reference)
#include <cuda_runtime.h>
#include <cstdint>

// ---------------------------------------------------------------------------
// MultiScaleRoIAlign (torchvision, aligned=False, SR=2) — warp-autonomous,
// SAMPLE-MAJOR compute. grid=(512 rois, 4 slices of 64 ch), block=256.
// Warp w owns channels {cbase + k*8 + w}; cp.async 3-buffer private ring.
// Compute: lane=(j2,k) sample coords; per step the 4 tap-LDS touch only 2
// window rows (few L1 wavefronts); bin = shuffle-reduction of 4 samples.
// Oversized windows (hr*rs2 > 512 float2) -> direct-global fallback.
// ---------------------------------------------------------------------------

#define WS2 512   // float2 slots per window buffer

__device__ __forceinline__ void cp_async8(uint32_t dst, const void* src, bool p)
{
    if (p) asm volatile("cp.async.ca.shared.global [%0], [%1], 8;"
                        :: "r"(dst), "l"(src) : "memory");
}
__device__ __forceinline__ void cp_async4(uint32_t dst, const void* src, bool p)
{
    if (p) asm volatile("cp.async.ca.shared.global [%0], [%1], 4;"
                        :: "r"(dst), "l"(src) : "memory");
}
#define CP_COMMIT()  asm volatile("cp.async.commit_group;" ::: "memory")
#define CP_WAIT(N)   asm volatile("cp.async.wait_group %0;" :: "n"(N) : "memory")

__global__ void __launch_bounds__(256, 2)
msroi_kernel(const float* __restrict__ f0, const float* __restrict__ f1,
             const float* __restrict__ f2, const float* __restrict__ f3,
             const float* __restrict__ boxes, float* __restrict__ out)
{
    __shared__ float2 win[8][3][WS2];                     // 96 KB
    __shared__ float s_hy[14], s_ly[14], s_hx[14], s_lx[14];
    __shared__ int   s_yl[14], s_yh[14], s_xl[14], s_xh[14];

    const int tid = threadIdx.x;
    const int n = blockIdx.x;

    float4 bx = __ldg(reinterpret_cast<const float4*>(boxes) + n);

    // LevelMapper: floor(4 + log2(sqrt(w*h)/224) + 1e-6), clip [2,5], -2
    float s = sqrtf((bx.z - bx.x) * (bx.w - bx.y));
    int lvl = (int)floorf(4.0f + log2f(s * (1.0f / 224.0f)) + 1e-6f);
    lvl = min(max(lvl, 2), 5) - 2;

    int H; float sc; const float* base;
    switch (lvl) {
        case 0:  H = 200; sc = 0.25f;    base = f0; break;
        case 1:  H = 100; sc = 0.125f;   base = f1; break;
        case 2:  H = 50;  sc = 0.0625f;  base = f2; break;
        default: H = 25;  sc = 0.03125f; base = f3; break;
    }
    const int HH = H * H;
    base += (size_t)(n >> 8) * 256 * HH;

    float x1s = bx.x * sc, y1s = bx.y * sc;
    float binw = fmaxf(bx.z * sc - x1s, 1.0f) * (1.0f / 7.0f);
    float binh = fmaxf(bx.w * sc - y1s, 1.0f) * (1.0f / 7.0f);
    float fH = (float)H;

    // window bounds
    int y0  = min((int)fmaxf(y1s + 0.25f * binh, 0.0f), H - 1);
    int x0  = min((int)fmaxf(x1s + 0.25f * binw, 0.0f), H - 1);
    int y1m = min((int)fmaxf(fminf(y1s + 6.75f * binh, fH - 1.0f), 0.0f) + 1, H - 1);
    int x1m = min((int)fmaxf(fminf(x1s + 6.75f * binw, fH - 1.0f), 0.0f) + 1, H - 1);
    const int hr  = y1m - y0 + 1;
    const int x0d = x0 & ~1;                   // float2-aligned window start
    const int wc2 = (x1m >> 1) - (x0d >> 1) + 1;
    const int rs2 = wc2 | 1;                   // odd float2 row stride
    const int rsF = rs2 * 2;                   // float row stride

    // per-sample bilinear params (14 y, 14 x), window-relative indices
    if (tid < 28) {
        bool isY = tid < 14;
        int j = isY ? tid : tid - 14;
        float o = (float)(j >> 1) + 0.25f + 0.5f * (float)(j & 1);
        float v = isY ? (y1s + o * binh) : (x1s + o * binw);
        bool valid = (v > -1.0f) && (v < fH);
        float vc = fmaxf(v, 0.0f);
        int lo = min((int)vc, H - 1);
        int hi = min(lo + 1, H - 1);
        float l = (lo >= H - 1) ? 0.0f : (vc - (float)lo);
        float h = 1.0f - l;
        if (!valid) { l = 0.0f; h = 0.0f; lo = isY ? y0 : x0d; hi = lo; }
        if (isY) { s_yl[j] = lo - y0;  s_yh[j] = hi - y0;  s_ly[j] = l; s_hy[j] = h; }
        else     { s_xl[j] = lo - x0d; s_xh[j] = hi - x0d; s_lx[j] = l; s_hx[j] = h; }
    }
    __syncthreads();                           // only block barrier

    const int warp = tid >> 5, lane = tid & 31;
    const int cbase = blockIdx.y * 64;

    // ---- sample-major lane map: lane = j2*14 + k  (lanes 28-31 idle) ----
    const int k14 = lane % 14;                 // x-sample index 0..13
    const int j2  = lane / 14;                 // 0,1 (2 for idle lanes)
    const float hx = s_hx[k14], lxw = s_lx[k14];
    const int   xfl = s_xl[k14], xfh = s_xh[k14];
    const bool  doStore = (lane < 14) && ((lane & 1) == 0);
    const int   oxs = lane >> 1;               // ox for storing lanes

    const bool fits = (hr * rs2) <= WS2;       // uniform per block
    const bool h25 = (H == 25);
    const int H2 = H >> 1;
    const int xlim = x1m - x0d;

    // staging lane geometry (32 lanes per window)
    const int wide = h25 ? (wc2 * 2) : wc2;    // elements per row (f32 / f2)
    int wp2 = 1;
    while (wp2 < wide && wp2 < 32) wp2 <<= 1;
    const int shift = __popc(wp2 - 1);
    const int rpw = 32 >> shift;               // rows per warp step
    const int lxe = lane & (wp2 - 1);
    const int lr0 = lane >> shift;

    float* outn = out + (size_t)n * 12544;

    if (fits) {
        auto stage = [&](int bf, int k) {
            const int cglob = cbase + k * 8 + warp;
            uint32_t wb = (uint32_t)__cvta_generic_to_shared(&win[warp][bf][0]);
            if (!h25) {
                const float2* src = reinterpret_cast<const float2*>(base)
                                  + (size_t)cglob * (HH >> 1) + y0 * H2 + (x0d >> 1);
                for (int cx0 = 0; cx0 < wc2; cx0 += wp2) {
                    int xx = cx0 + lxe;
                    bool inx = xx < wc2;
                    for (int r = lr0; r < hr; r += rpw)
                        cp_async8(wb + (uint32_t)(r * rs2 + xx) * 8u,
                                  src + r * H2 + xx, inx);
                }
            } else {
                const float* src = base + (size_t)cglob * HH + y0 * H + x0d;
                for (int cx0 = 0; cx0 < wide; cx0 += wp2) {
                    int xx = cx0 + lxe;
                    bool inx = xx <= xlim;
                    for (int r = lr0; r < hr; r += rpw)
                        cp_async4(wb + (uint32_t)(r * rsF + xx) * 4u,
                                  src + r * H + xx, inx);
                }
            }
        };

        stage(0, 0); CP_COMMIT();
        stage(1, 1); CP_COMMIT();

        #pragma unroll 1
        for (int k = 0; k < 8; k++) {
            int bf = k % 3;
            if (k + 2 < 8) {
                stage((k + 2) % 3, k + 2);
                CP_COMMIT();
                CP_WAIT(2);
            } else if (k + 1 < 8) {
                CP_WAIT(1);
            } else {
                CP_WAIT(0);
            }
            __syncwarp();

            const float* W = reinterpret_cast<const float*>(win[warp][bf]);
            float* on = outn + (cbase + k * 8 + warp) * 49;

            #pragma unroll 1
            for (int step = 0; step < 7; step++) {
                int j = min(step * 2 + j2, 13);
                float hy = s_hy[j], ly = s_ly[j];
                int r0 = s_yl[j] * rsF, r1 = s_yh[j] * rsF;

                // 4 taps: only 2 distinct window rows per warp-LDS
                float v = hy * (hx * W[r0 + xfl] + lxw * W[r0 + xfh])
                        + ly * (hx * W[r1 + xfl] + lxw * W[r1 + xfh]);
                // reduce x-sample pair, then y-sample pair
                float u = v + __shfl_down_sync(0xffffffffu, v, 1);
                float bsum = u + __shfl_down_sync(0xffffffffu, u, 14);
                if (doStore)
                    on[step * 7 + oxs] = bsum * 0.25f;
            }
            __syncwarp();
        }
    } else {
        // ---- rare oversized window: direct global gather, one bin/lane ----
        #pragma unroll 1
        for (int k = 0; k < 8; k++) {
            const int cglob = cbase + k * 8 + warp;
            const float* src = base + (size_t)cglob * HH;
            #pragma unroll 1
            for (int half = 0; half < 2; half++) {
                int bin = half * 32 + lane;
                if (bin >= 49) break;
                int oy = bin / 7, ox = bin - oy * 7;
                float acc = 0.0f;
                #pragma unroll
                for (int sy = 0; sy < 2; sy++) {
                    int j = oy * 2 + sy;
                    float hy = s_hy[j], ly = s_ly[j];
                    int ra = (s_yl[j] + y0) * H, rb = (s_yh[j] + y0) * H;
                    #pragma unroll
                    for (int sx = 0; sx < 2; sx++) {
                        int kk = ox * 2 + sx;
                        float hxx = s_hx[kk], lxx = s_lx[kk];
                        int xa = s_xl[kk] + x0d, xb = s_xh[kk] + x0d;
                        acc += hy * (hxx * __ldg(src + ra + xa) + lxx * __ldg(src + ra + xb))
                             + ly * (hxx * __ldg(src + rb + xa) + lxx * __ldg(src + rb + xb));
                    }
                }
                outn[cglob * 49 + bin] = acc * 0.25f;
            }
        }
    }
}

extern "C" void kernel_launch(void* const* d_in, const int* in_sizes, int n_in,
                              void* d_out, int out_size)
{
    const float* f0 = (const float*)d_in[0];
    const float* f1 = (const float*)d_in[1];
    const float* f2 = (const float*)d_in[2];
    const float* f3 = (const float*)d_in[3];
    const float* boxes = (const float*)d_in[4];
    float* out = (float*)d_out;

    msroi_kernel<<<dim3(512, 4), 256>>>(f0, f1, f2, f3, boxes, out);
}

// round 12
// speedup vs baseline: 1.0398x; 1.0398x over previous
#include <cuda_runtime.h>
#include <cstdint>

// ---------------------------------------------------------------------------
// MultiScaleRoIAlign (torchvision, aligned=False, SR=2) — direct-gather.
// grid=(512 rois, 4 slices of 64 ch), block=256 (8 warps).
// No smem staging: each warp owns 8 channels; each lane owns bin A=lane and
// bin B=32+lane (lane<17) with bilinear params held in registers as absolute
// (row*H, x) element offsets. Per channel: 16(+16) independent __ldg taps
// (MLP~32, L1D-cached window, ~3.5x reuse) + FMA tree + coalesced stores.
// ---------------------------------------------------------------------------

__global__ void __launch_bounds__(256, 3)
msroi_kernel(const float* __restrict__ f0, const float* __restrict__ f1,
             const float* __restrict__ f2, const float* __restrict__ f3,
             const float* __restrict__ boxes, float* __restrict__ out)
{
    __shared__ float s_hy[14], s_ly[14], s_hx[14], s_lx[14];
    __shared__ int   s_yr[14], s_yR[14], s_xl[14], s_xh[14];

    const int tid = threadIdx.x;
    const int n = blockIdx.x;

    float4 bx = __ldg(reinterpret_cast<const float4*>(boxes) + n);

    // LevelMapper: floor(4 + log2(sqrt(w*h)/224) + 1e-6), clip [2,5], -2
    float s = sqrtf((bx.z - bx.x) * (bx.w - bx.y));
    int lvl = (int)floorf(4.0f + log2f(s * (1.0f / 224.0f)) + 1e-6f);
    lvl = min(max(lvl, 2), 5) - 2;

    int H; float sc; const float* base;
    switch (lvl) {
        case 0:  H = 200; sc = 0.25f;    base = f0; break;
        case 1:  H = 100; sc = 0.125f;   base = f1; break;
        case 2:  H = 50;  sc = 0.0625f;  base = f2; break;
        default: H = 25;  sc = 0.03125f; base = f3; break;
    }
    const int HH = H * H;
    base += (size_t)(n >> 8) * 256 * HH;

    float x1s = bx.x * sc, y1s = bx.y * sc;
    float binw = fmaxf(bx.z * sc - x1s, 1.0f) * (1.0f / 7.0f);
    float binh = fmaxf(bx.w * sc - y1s, 1.0f) * (1.0f / 7.0f);
    float fH = (float)H;

    // per-sample bilinear params (14 y, 14 x); absolute coords, row pre-*H.
    // invalid sample -> weights 0, indices 0 (safe reads).
    if (tid < 28) {
        bool isY = tid < 14;
        int j = isY ? tid : tid - 14;
        float o = (float)(j >> 1) + 0.25f + 0.5f * (float)(j & 1);
        float v = isY ? (y1s + o * binh) : (x1s + o * binw);
        bool valid = (v > -1.0f) && (v < fH);
        float vc = fmaxf(v, 0.0f);
        int lo = min((int)vc, H - 1);
        int hi = min(lo + 1, H - 1);
        float l = (lo >= H - 1) ? 0.0f : (vc - (float)lo);
        float h = 1.0f - l;
        if (!valid) { l = 0.0f; h = 0.0f; lo = 0; hi = 0; }
        if (isY) { s_yr[j] = lo * H; s_yR[j] = hi * H; s_ly[j] = l; s_hy[j] = h; }
        else     { s_xl[j] = lo;     s_xh[j] = hi;     s_lx[j] = l; s_hx[j] = h; }
    }
    __syncthreads();

    const int warp = tid >> 5, lane = tid & 31;
    const int cbase = blockIdx.y * 64;

    // ---- bin A = lane ----
    int Ar0a, Ar1a, Ar0b, Ar1b, Axl0, Axh0, Axl1, Axh1;
    float Ahy0, Aly0, Ahy1, Aly1, Ahx0, Alx0, Ahx1, Alx1;
    {
        int bin = lane > 48 ? 48 : lane;       // lane<=31 anyway; keep safe
        int oy = bin / 7, ox = bin - oy * 7;
        int j0 = oy * 2, j1 = j0 + 1, k0 = ox * 2, k1 = k0 + 1;
        Ar0a = s_yr[j0]; Ar1a = s_yR[j0]; Ar0b = s_yr[j1]; Ar1b = s_yR[j1];
        Axl0 = s_xl[k0]; Axh0 = s_xh[k0]; Axl1 = s_xl[k1]; Axh1 = s_xh[k1];
        Ahy0 = s_hy[j0]; Aly0 = s_ly[j0]; Ahy1 = s_hy[j1]; Aly1 = s_ly[j1];
        Ahx0 = s_hx[k0]; Alx0 = s_lx[k0]; Ahx1 = s_hx[k1]; Alx1 = s_lx[k1];
    }
    // ---- bin B = 32 + lane (active for lane<17) ----
    const bool hasB = lane < 17;
    int Br0a = 0, Br1a = 0, Br0b = 0, Br1b = 0, Bxl0 = 0, Bxh0 = 0, Bxl1 = 0, Bxh1 = 0;
    float Bhy0 = 0, Bly0 = 0, Bhy1 = 0, Bly1 = 0, Bhx0 = 0, Blx0 = 0, Bhx1 = 0, Blx1 = 0;
    if (hasB) {
        int bin = 32 + lane;
        int oy = bin / 7, ox = bin - oy * 7;
        int j0 = oy * 2, j1 = j0 + 1, k0 = ox * 2, k1 = k0 + 1;
        Br0a = s_yr[j0]; Br1a = s_yR[j0]; Br0b = s_yr[j1]; Br1b = s_yR[j1];
        Bxl0 = s_xl[k0]; Bxh0 = s_xh[k0]; Bxl1 = s_xl[k1]; Bxh1 = s_xh[k1];
        Bhy0 = s_hy[j0]; Bly0 = s_ly[j0]; Bhy1 = s_hy[j1]; Bly1 = s_ly[j1];
        Bhx0 = s_hx[k0]; Blx0 = s_lx[k0]; Bhx1 = s_hx[k1]; Blx1 = s_lx[k1];
    }

    float* outn = out + (size_t)n * 12544;
    const float* src = base + (size_t)(cbase + warp) * HH;

    #pragma unroll 1
    for (int k = 0; k < 8; k++) {
        // ---- bin A: 16 independent cached-global taps ----
        float a00 = __ldg(src + Ar0a + Axl0);
        float a01 = __ldg(src + Ar0a + Axh0);
        float a02 = __ldg(src + Ar1a + Axl0);
        float a03 = __ldg(src + Ar1a + Axh0);
        float a04 = __ldg(src + Ar0a + Axl1);
        float a05 = __ldg(src + Ar0a + Axh1);
        float a06 = __ldg(src + Ar1a + Axl1);
        float a07 = __ldg(src + Ar1a + Axh1);
        float a08 = __ldg(src + Ar0b + Axl0);
        float a09 = __ldg(src + Ar0b + Axh0);
        float a10 = __ldg(src + Ar1b + Axl0);
        float a11 = __ldg(src + Ar1b + Axh0);
        float a12 = __ldg(src + Ar0b + Axl1);
        float a13 = __ldg(src + Ar0b + Axh1);
        float a14 = __ldg(src + Ar1b + Axl1);
        float a15 = __ldg(src + Ar1b + Axh1);

        float accA =
              Ahy0 * (Ahx0 * a00 + Alx0 * a01) + Aly0 * (Ahx0 * a02 + Alx0 * a03)
            + Ahy0 * (Ahx1 * a04 + Alx1 * a05) + Aly0 * (Ahx1 * a06 + Alx1 * a07)
            + Ahy1 * (Ahx0 * a08 + Alx0 * a09) + Aly1 * (Ahx0 * a10 + Alx0 * a11)
            + Ahy1 * (Ahx1 * a12 + Alx1 * a13) + Aly1 * (Ahx1 * a14 + Alx1 * a15);

        float accB = 0.0f;
        if (hasB) {
            float b00 = __ldg(src + Br0a + Bxl0);
            float b01 = __ldg(src + Br0a + Bxh0);
            float b02 = __ldg(src + Br1a + Bxl0);
            float b03 = __ldg(src + Br1a + Bxh0);
            float b04 = __ldg(src + Br0a + Bxl1);
            float b05 = __ldg(src + Br0a + Bxh1);
            float b06 = __ldg(src + Br1a + Bxl1);
            float b07 = __ldg(src + Br1a + Bxh1);
            float b08 = __ldg(src + Br0b + Bxl0);
            float b09 = __ldg(src + Br0b + Bxh0);
            float b10 = __ldg(src + Br1b + Bxl0);
            float b11 = __ldg(src + Br1b + Bxh0);
            float b12 = __ldg(src + Br0b + Bxl1);
            float b13 = __ldg(src + Br0b + Bxh1);
            float b14 = __ldg(src + Br1b + Bxl1);
            float b15 = __ldg(src + Br1b + Bxh1);
            accB =
                  Bhy0 * (Bhx0 * b00 + Blx0 * b01) + Bly0 * (Bhx0 * b02 + Blx0 * b03)
                + Bhy0 * (Bhx1 * b04 + Blx1 * b05) + Bly0 * (Bhx1 * b06 + Blx1 * b07)
                + Bhy1 * (Bhx0 * b08 + Blx0 * b09) + Bly1 * (Bhx0 * b10 + Blx0 * b11)
                + Bhy1 * (Bhx1 * b12 + Blx1 * b13) + Bly1 * (Bhx1 * b14 + Blx1 * b15);
        }

        float* on = outn + (cbase + k * 8 + warp) * 49;
        on[lane] = accA * 0.25f;
        if (hasB) on[32 + lane] = accB * 0.25f;

        src += 8 * HH;                          // next owned channel
    }
}

extern "C" void kernel_launch(void* const* d_in, const int* in_sizes, int n_in,
                              void* d_out, int out_size)
{
    const float* f0 = (const float*)d_in[0];
    const float* f1 = (const float*)d_in[1];
    const float* f2 = (const float*)d_in[2];
    const float* f3 = (const float*)d_in[3];
    const float* boxes = (const float*)d_in[4];
    float* out = (float*)d_out;

    msroi_kernel<<<dim3(512, 4), 256>>>(f0, f1, f2, f3, boxes, out);
}

// round 13
// speedup vs baseline: 1.2677x; 1.2192x over previous
#include <cuda_runtime.h>
#include <cstdint>

// ---------------------------------------------------------------------------
// MultiScaleRoIAlign (torchvision, aligned=False, SR=2) — channel-pair
// interleaved windows. grid=(512 rois, 4 slices of 64 ch), block=256
// (8 warps = 4 warp-pairs). Pair p owns 16 channels as 8 chunks of 2;
// window smem holds float2 (chA[x], chB[x]) so ONE LDS.64 feeds both
// channels of a tap: per chunk = 16 LDS.64 + 32 FFMA (weights & slot
// offsets precombined in registers). cp.async element staging, 3-buffer
// ring, prefetch 2, pair-scoped named barriers.
// Capacity: hr*rsX <= 1024 floats holds for all level-mapped boxes
// (s_scaled < 28, w_scaled <= 147.5 -> max ~990); fallback kept for safety.
// ---------------------------------------------------------------------------

#define WSF 1024   // float2 slots per window buffer (channel-pair)

__device__ __forceinline__ void cp_async4(uint32_t dst, const void* src, bool p)
{
    if (p) asm volatile("cp.async.ca.shared.global [%0], [%1], 4;"
                        :: "r"(dst), "l"(src) : "memory");
}
#define CP_COMMIT()  asm volatile("cp.async.commit_group;" ::: "memory")
#define CP_WAIT(N)   asm volatile("cp.async.wait_group %0;" :: "n"(N) : "memory")

__global__ void __launch_bounds__(256)
msroi_kernel(const float* __restrict__ f0, const float* __restrict__ f1,
             const float* __restrict__ f2, const float* __restrict__ f3,
             const float* __restrict__ boxes, float* __restrict__ out)
{
    __shared__ float2 win[4][3][WSF];                     // 98.3 KB
    __shared__ float s_hy[14], s_ly[14], s_hx[14], s_lx[14];
    __shared__ int   s_yl[14], s_yh[14], s_xl[14], s_xh[14];

    const int tid = threadIdx.x;
    const int n = blockIdx.x;

    float4 bx = __ldg(reinterpret_cast<const float4*>(boxes) + n);

    // LevelMapper: floor(4 + log2(sqrt(w*h)/224) + 1e-6), clip [2,5], -2
    float s = sqrtf((bx.z - bx.x) * (bx.w - bx.y));
    int lvl = (int)floorf(4.0f + log2f(s * (1.0f / 224.0f)) + 1e-6f);
    lvl = min(max(lvl, 2), 5) - 2;

    int H; float sc; const float* base;
    switch (lvl) {
        case 0:  H = 200; sc = 0.25f;    base = f0; break;
        case 1:  H = 100; sc = 0.125f;   base = f1; break;
        case 2:  H = 50;  sc = 0.0625f;  base = f2; break;
        default: H = 25;  sc = 0.03125f; base = f3; break;
    }
    const int HH = H * H;
    base += (size_t)(n >> 8) * 256 * HH;

    float x1s = bx.x * sc, y1s = bx.y * sc;
    float binw = fmaxf(bx.z * sc - x1s, 1.0f) * (1.0f / 7.0f);
    float binh = fmaxf(bx.w * sc - y1s, 1.0f) * (1.0f / 7.0f);
    float fH = (float)H;

    // window bounds (exact x0; element-wise staging needs no alignment)
    int y0  = min((int)fmaxf(y1s + 0.25f * binh, 0.0f), H - 1);
    int x0  = min((int)fmaxf(x1s + 0.25f * binw, 0.0f), H - 1);
    int y1m = min((int)fmaxf(fminf(y1s + 6.75f * binh, fH - 1.0f), 0.0f) + 1, H - 1);
    int x1m = min((int)fmaxf(fminf(x1s + 6.75f * binw, fH - 1.0f), 0.0f) + 1, H - 1);
    const int hr  = y1m - y0 + 1;
    const int wcF = x1m - x0 + 1;              // floats per row
    const int rsX = wcF | 1;                   // odd float row stride

    // per-sample bilinear params (14 y, 14 x), window-relative
    if (tid < 28) {
        bool isY = tid < 14;
        int j = isY ? tid : tid - 14;
        float o = (float)(j >> 1) + 0.25f + 0.5f * (float)(j & 1);
        float v = isY ? (y1s + o * binh) : (x1s + o * binw);
        bool valid = (v > -1.0f) && (v < fH);
        float vc = fmaxf(v, 0.0f);
        int lo = min((int)vc, H - 1);
        int hi = min(lo + 1, H - 1);
        float l = (lo >= H - 1) ? 0.0f : (vc - (float)lo);
        float h = 1.0f - l;
        if (!valid) { l = 0.0f; h = 0.0f; lo = isY ? y0 : x0; hi = lo; }
        if (isY) { s_yl[j] = lo - y0; s_yh[j] = hi - y0; s_ly[j] = l; s_hy[j] = h; }
        else     { s_xl[j] = lo - x0; s_xh[j] = hi - x0; s_lx[j] = l; s_hx[j] = h; }
    }
    __syncthreads();                           // only block barrier

    const int warp = tid >> 5, lane = tid & 31;
    const int pair = warp >> 1, wsub = warp & 1;
    const int q = wsub * 32 + lane;            // 0..63 within pair
    const int cbase = blockIdx.y * 64;

    // bin per lane: warp0 -> bins 0-31, warp1 -> bins 32-48 (lane<17)
    const int binRaw = wsub ? (32 + lane) : lane;
    const bool act = wsub ? (lane < 17) : true;
    const int bin = min(binRaw, 48);

    // ---- 16 precombined tap offsets (float2 slots) + scalar weights ----
    int   toff[16];
    float twgt[16];
    {
        int oy = bin / 7, ox = bin - oy * 7;
        int j0 = oy * 2, j1 = j0 + 1, k0 = ox * 2, k1 = k0 + 1;
        int   R[4]  = { s_yl[j0] * rsX, s_yh[j0] * rsX,
                        s_yl[j1] * rsX, s_yh[j1] * rsX };
        float WY[4] = { s_hy[j0], s_ly[j0], s_hy[j1], s_ly[j1] };
        int   C[4]  = { s_xl[k0], s_xh[k0], s_xl[k1], s_xh[k1] };
        float WX[4] = { s_hx[k0], s_lx[k0], s_hx[k1], s_lx[k1] };
        #pragma unroll
        for (int a = 0; a < 4; a++)
            #pragma unroll
            for (int bcol = 0; bcol < 4; bcol++) {
                toff[a * 4 + bcol] = R[a] + C[bcol];
                twgt[a * 4 + bcol] = WY[a] * WX[bcol];
            }
    }

    const bool fits = (hr * rsX) <= WSF;       // uniform per block
    // staging geometry: 64 lanes cover wp2 x-positions x (64/wp2) rows
    int wp2 = 1;
    while (wp2 < wcF && wp2 < 64) wp2 <<= 1;
    const int shift = __popc(wp2 - 1);
    const int rpw = 64 >> shift;
    const int lxe = q & (wp2 - 1);
    const int lr0 = q >> shift;

    float* outn = out + (size_t)n * 12544;
    const int barid = pair + 1;

    if (fits) {
        auto stage = [&](int bf, int k) {
            const int c0 = cbase + pair * 16 + k * 2;
            const float* sA = base + (size_t)c0 * HH + y0 * H + x0;
            const float* sB = sA + HH;
            uint32_t wb = (uint32_t)__cvta_generic_to_shared(&win[pair][bf][0]);
            for (int cx0 = 0; cx0 < wcF; cx0 += wp2) {
                int cx = cx0 + lxe;
                bool inx = cx < wcF;
                for (int r = lr0; r < hr; r += rpw) {
                    uint32_t e8 = (uint32_t)(r * rsX + cx) * 8u;
                    cp_async4(wb + e8,      sA + r * H + cx, inx);
                    cp_async4(wb + e8 + 4u, sB + r * H + cx, inx);
                }
            }
        };

        stage(0, 0); CP_COMMIT();
        stage(1, 1); CP_COMMIT();

        #pragma unroll 1
        for (int k = 0; k < 8; k++) {
            int bf = k % 3;
            if (k + 2 < 8) {
                stage((k + 2) % 3, k + 2);
                CP_COMMIT();
                CP_WAIT(2);
            } else if (k + 1 < 8) {
                CP_WAIT(1);
            } else {
                CP_WAIT(0);
            }
            // barrier A: partner warp's copies for buf k%3 landed too
            asm volatile("bar.sync %0, 64;" :: "r"(barid) : "memory");

            const float2* W = win[pair][bf];
            float ax = 0.0f, ay = 0.0f;
            #pragma unroll
            for (int i = 0; i < 16; i++) {
                float2 t = W[toff[i]];         // one LDS.64 feeds 2 channels
                ax += twgt[i] * t.x;
                ay += twgt[i] * t.y;
            }
            if (act) {
                const int c0 = cbase + pair * 16 + k * 2;
                outn[c0 * 49 + binRaw]      = ax * 0.25f;
                outn[c0 * 49 + 49 + binRaw] = ay * 0.25f;
            }
            // barrier B: both warps done reading buf before restage
            asm volatile("bar.sync %0, 64;" :: "r"(barid) : "memory");
        }
    } else {
        // safety net (unreachable by level-mapper bound): direct gather
        #pragma unroll 1
        for (int k = 0; k < 16; k++) {
            const int cglob = cbase + pair * 16 + k;
            const float* src = base + (size_t)cglob * HH;
            int oy = bin / 7, ox = bin - oy * 7;
            float acc = 0.0f;
            #pragma unroll
            for (int sy = 0; sy < 2; sy++) {
                int j = oy * 2 + sy;
                float hy = s_hy[j], ly = s_ly[j];
                int ra = (s_yl[j] + y0) * H, rb = (s_yh[j] + y0) * H;
                #pragma unroll
                for (int sx = 0; sx < 2; sx++) {
                    int kk = ox * 2 + sx;
                    float hx = s_hx[kk], lx = s_lx[kk];
                    int xa = s_xl[kk] + x0, xb = s_xh[kk] + x0;
                    acc += hy * (hx * __ldg(src + ra + xa) + lx * __ldg(src + ra + xb))
                         + ly * (hx * __ldg(src + rb + xa) + lx * __ldg(src + rb + xb));
                }
            }
            if (act)
                outn[cglob * 49 + binRaw] = acc * 0.25f;
        }
    }
}

extern "C" void kernel_launch(void* const* d_in, const int* in_sizes, int n_in,
                              void* d_out, int out_size)
{
    const float* f0 = (const float*)d_in[0];
    const float* f1 = (const float*)d_in[1];
    const float* f2 = (const float*)d_in[2];
    const float* f3 = (const float*)d_in[3];
    const float* boxes = (const float*)d_in[4];
    float* out = (float*)d_out;

    msroi_kernel<<<dim3(512, 4), 256>>>(f0, f1, f2, f3, boxes, out);
}

// round 14
// speedup vs baseline: 1.4023x; 1.1061x over previous
#include <cuda_runtime.h>
#include <cstdint>

// ---------------------------------------------------------------------------
// MultiScaleRoIAlign (torchvision, aligned=False, SR=2) — warp-autonomous
// (r8 skeleton) with flattened staging + precombined tap offsets.
// grid=(512 rois, 4 slices of 64 ch), block=256 (8 warps).
// Warp w owns channels {cbase + k*8 + w}; cp.async8 3-buffer private ring,
// prefetch distance 2; lane computes bins lane and 32+lane (lane<17).
// Oversized windows (hr*rs2 > 512 float2) -> direct-global fallback.
// ---------------------------------------------------------------------------

#define WS2 512   // float2 slots per window buffer

__device__ __forceinline__ void cp_a8(uint32_t dst, const void* src)
{
    asm volatile("cp.async.ca.shared.global [%0], [%1], 8;"
                 :: "r"(dst), "l"(src) : "memory");
}
__device__ __forceinline__ void cp_a4(uint32_t dst, const void* src)
{
    asm volatile("cp.async.ca.shared.global [%0], [%1], 4;"
                 :: "r"(dst), "l"(src) : "memory");
}
#define CP_COMMIT()  asm volatile("cp.async.commit_group;" ::: "memory")
#define CP_WAIT(N)   asm volatile("cp.async.wait_group %0;" :: "n"(N) : "memory")

__global__ void __launch_bounds__(256, 2)
msroi_kernel(const float* __restrict__ f0, const float* __restrict__ f1,
             const float* __restrict__ f2, const float* __restrict__ f3,
             const float* __restrict__ boxes, float* __restrict__ out)
{
    __shared__ float2 win[8][3][WS2];                     // 96 KB
    __shared__ float s_hy[14], s_ly[14], s_hx[14], s_lx[14];
    __shared__ int   s_yl[14], s_yh[14], s_xl[14], s_xh[14];

    const int tid = threadIdx.x;
    const int n = blockIdx.x;

    float4 bx = __ldg(reinterpret_cast<const float4*>(boxes) + n);

    // LevelMapper: floor(4 + log2(sqrt(w*h)/224) + 1e-6), clip [2,5], -2
    float s = sqrtf((bx.z - bx.x) * (bx.w - bx.y));
    int lvl = (int)floorf(4.0f + log2f(s * (1.0f / 224.0f)) + 1e-6f);
    lvl = min(max(lvl, 2), 5) - 2;

    int H; float sc; const float* base;
    switch (lvl) {
        case 0:  H = 200; sc = 0.25f;    base = f0; break;
        case 1:  H = 100; sc = 0.125f;   base = f1; break;
        case 2:  H = 50;  sc = 0.0625f;  base = f2; break;
        default: H = 25;  sc = 0.03125f; base = f3; break;
    }
    const int HH = H * H;
    base += (size_t)(n >> 8) * 256 * HH;

    float x1s = bx.x * sc, y1s = bx.y * sc;
    float binw = fmaxf(bx.z * sc - x1s, 1.0f) * (1.0f / 7.0f);
    float binh = fmaxf(bx.w * sc - y1s, 1.0f) * (1.0f / 7.0f);
    float fH = (float)H;

    // window bounds
    int y0  = min((int)fmaxf(y1s + 0.25f * binh, 0.0f), H - 1);
    int x0  = min((int)fmaxf(x1s + 0.25f * binw, 0.0f), H - 1);
    int y1m = min((int)fmaxf(fminf(y1s + 6.75f * binh, fH - 1.0f), 0.0f) + 1, H - 1);
    int x1m = min((int)fmaxf(fminf(x1s + 6.75f * binw, fH - 1.0f), 0.0f) + 1, H - 1);
    const int hr  = y1m - y0 + 1;
    const int x0d = x0 & ~1;                   // float2-aligned window start
    const int wc2 = (x1m >> 1) - (x0d >> 1) + 1;
    const int rs2 = wc2 | 1;                   // odd float2 row stride
    const int rsF = rs2 * 2;                   // float row stride

    // per-sample bilinear params (14 y, 14 x), window-relative indices
    if (tid < 28) {
        bool isY = tid < 14;
        int j = isY ? tid : tid - 14;
        float o = (float)(j >> 1) + 0.25f + 0.5f * (float)(j & 1);
        float v = isY ? (y1s + o * binh) : (x1s + o * binw);
        bool valid = (v > -1.0f) && (v < fH);
        float vc = fmaxf(v, 0.0f);
        int lo = min((int)vc, H - 1);
        int hi = min(lo + 1, H - 1);
        float l = (lo >= H - 1) ? 0.0f : (vc - (float)lo);
        float h = 1.0f - l;
        if (!valid) { l = 0.0f; h = 0.0f; lo = isY ? y0 : x0d; hi = lo; }
        if (isY) { s_yl[j] = lo - y0;  s_yh[j] = hi - y0;  s_ly[j] = l; s_hy[j] = h; }
        else     { s_xl[j] = lo - x0d; s_xh[j] = hi - x0d; s_lx[j] = l; s_hx[j] = h; }
    }
    __syncthreads();                           // only block barrier

    const int warp = tid >> 5, lane = tid & 31;
    const int cbase = blockIdx.y * 64;

    // ---- per-lane params: bins A=lane, B=32+lane (lane<17) ----
    // 16 precombined float-element offsets per bin + 8 weights per bin.
    int toffA[16], toffB[16];
    float Ahy0, Aly0, Ahy1, Aly1, Ahx0, Alx0, Ahx1, Alx1;
    float Bhy0 = 0, Bly0 = 0, Bhy1 = 0, Bly1 = 0;
    float Bhx0 = 0, Blx0 = 0, Bhx1 = 0, Blx1 = 0;
    const bool hasB = lane < 17;
    {
        int bin = lane;
        int oy = bin / 7, ox = bin - oy * 7;
        int j0 = oy * 2, j1 = j0 + 1, k0 = ox * 2, k1 = k0 + 1;
        int R0 = s_yl[j0] * rsF, R1 = s_yh[j0] * rsF;
        int R2 = s_yl[j1] * rsF, R3 = s_yh[j1] * rsF;
        int C0 = s_xl[k0], C1 = s_xh[k0], C2 = s_xl[k1], C3 = s_xh[k1];
        toffA[0]=R0+C0; toffA[1]=R0+C1; toffA[2]=R1+C0; toffA[3]=R1+C1;
        toffA[4]=R0+C2; toffA[5]=R0+C3; toffA[6]=R1+C2; toffA[7]=R1+C3;
        toffA[8]=R2+C0; toffA[9]=R2+C1; toffA[10]=R3+C0; toffA[11]=R3+C1;
        toffA[12]=R2+C2; toffA[13]=R2+C3; toffA[14]=R3+C2; toffA[15]=R3+C3;
        Ahy0=s_hy[j0]; Aly0=s_ly[j0]; Ahy1=s_hy[j1]; Aly1=s_ly[j1];
        Ahx0=s_hx[k0]; Alx0=s_lx[k0]; Ahx1=s_hx[k1]; Alx1=s_lx[k1];
    }
    {
        int bin = hasB ? (32 + lane) : 48;
        int oy = bin / 7, ox = bin - oy * 7;
        int j0 = oy * 2, j1 = j0 + 1, k0 = ox * 2, k1 = k0 + 1;
        int R0 = s_yl[j0] * rsF, R1 = s_yh[j0] * rsF;
        int R2 = s_yl[j1] * rsF, R3 = s_yh[j1] * rsF;
        int C0 = s_xl[k0], C1 = s_xh[k0], C2 = s_xl[k1], C3 = s_xh[k1];
        toffB[0]=R0+C0; toffB[1]=R0+C1; toffB[2]=R1+C0; toffB[3]=R1+C1;
        toffB[4]=R0+C2; toffB[5]=R0+C3; toffB[6]=R1+C2; toffB[7]=R1+C3;
        toffB[8]=R2+C0; toffB[9]=R2+C1; toffB[10]=R3+C0; toffB[11]=R3+C1;
        toffB[12]=R2+C2; toffB[13]=R2+C3; toffB[14]=R3+C2; toffB[15]=R3+C3;
        if (hasB) {
            Bhy0=s_hy[j0]; Bly0=s_ly[j0]; Bhy1=s_hy[j1]; Bly1=s_ly[j1];
            Bhx0=s_hx[k0]; Blx0=s_lx[k0]; Bhx1=s_hx[k1]; Blx1=s_lx[k1];
        }
    }

    const bool fits = (hr * rs2) <= WS2;       // uniform per block
    const bool h25 = (H == 25);
    const int H2 = H >> 1;
    const int xlim = x1m - x0d;

    // staging lane geometry (32 lanes per window)
    const int wide = h25 ? (xlim + 1) : wc2;   // elements per row (f32 / f2)
    int wp2 = 1;
    while (wp2 < wide && wp2 < 32) wp2 <<= 1;
    const int shift = __popc(wp2 - 1);
    const int rpw = 32 >> shift;               // rows per warp step
    const int lxe = lane & (wp2 - 1);
    const int lr0 = lane >> shift;

    float* outn = out + (size_t)n * 12544;

    if (fits) {
        // per-lane staging constants (pointer-increment loops)
        const int gstep2 = rpw * H2;           // float2 step (!h25 path)
        const int sstep2 = rpw * rs2 * 8;      // smem byte step (!h25)
        const int gstepF = rpw * H;            // float step (h25 path)
        const int sstepF = rpw * rsF * 4;      // smem byte step (h25)

        auto stage = [&](int bf, int k) {
            const int cglob = cbase + k * 8 + warp;
            uint32_t wb = (uint32_t)__cvta_generic_to_shared(&win[warp][bf][0]);
            if (!h25) {
                const float2* g = reinterpret_cast<const float2*>(base)
                                + (size_t)cglob * (HH >> 1) + y0 * H2 + (x0d >> 1);
                if (wide <= 32) {              // common: one x-pass
                    if (lxe < wc2) {
                        const float2* gp = g + lr0 * H2 + lxe;
                        uint32_t sa = wb + (uint32_t)(lr0 * rs2 + lxe) * 8u;
                        for (int r = lr0; r < hr; r += rpw) {
                            cp_a8(sa, gp);
                            gp += gstep2; sa += (uint32_t)sstep2;
                        }
                    }
                } else {                       // rare wide window
                    for (int cx0 = 0; cx0 < wc2; cx0 += wp2) {
                        int xx = cx0 + lxe;
                        if (xx >= wc2) break;
                        const float2* gp = g + lr0 * H2 + xx;
                        uint32_t sa = wb + (uint32_t)(lr0 * rs2 + xx) * 8u;
                        for (int r = lr0; r < hr; r += rpw) {
                            cp_a8(sa, gp);
                            gp += gstep2; sa += (uint32_t)sstep2;
                        }
                    }
                }
            } else {                           // H=25: wide<=25, one x-pass
                const float* g = base + (size_t)cglob * HH + y0 * H + x0d;
                if (lxe <= xlim) {
                    const float* gp = g + lr0 * H + lxe;
                    uint32_t sa = wb + (uint32_t)(lr0 * rsF + lxe) * 4u;
                    for (int r = lr0; r < hr; r += rpw) {
                        cp_a4(sa, gp);
                        gp += gstepF; sa += (uint32_t)sstepF;
                    }
                }
            }
        };

        stage(0, 0); CP_COMMIT();
        stage(1, 1); CP_COMMIT();

        #pragma unroll 1
        for (int k = 0; k < 8; k++) {
            int bf = k % 3;
            if (k + 2 < 8) {
                stage((k + 2) % 3, k + 2);
                CP_COMMIT();
                CP_WAIT(2);
            } else if (k + 1 < 8) {
                CP_WAIT(1);
            } else {
                CP_WAIT(0);
            }
            __syncwarp();

            const float* W = reinterpret_cast<const float*>(win[warp][bf]);
            float accA =
                  Ahy0 * (Ahx0 * W[toffA[0]]  + Alx0 * W[toffA[1]])
                + Aly0 * (Ahx0 * W[toffA[2]]  + Alx0 * W[toffA[3]])
                + Ahy0 * (Ahx1 * W[toffA[4]]  + Alx1 * W[toffA[5]])
                + Aly0 * (Ahx1 * W[toffA[6]]  + Alx1 * W[toffA[7]])
                + Ahy1 * (Ahx0 * W[toffA[8]]  + Alx0 * W[toffA[9]])
                + Aly1 * (Ahx0 * W[toffA[10]] + Alx0 * W[toffA[11]])
                + Ahy1 * (Ahx1 * W[toffA[12]] + Alx1 * W[toffA[13]])
                + Aly1 * (Ahx1 * W[toffA[14]] + Alx1 * W[toffA[15]]);
            float accB = 0.0f;
            if (hasB) {
                accB =
                      Bhy0 * (Bhx0 * W[toffB[0]]  + Blx0 * W[toffB[1]])
                    + Bly0 * (Bhx0 * W[toffB[2]]  + Blx0 * W[toffB[3]])
                    + Bhy0 * (Bhx1 * W[toffB[4]]  + Blx1 * W[toffB[5]])
                    + Bly0 * (Bhx1 * W[toffB[6]]  + Blx1 * W[toffB[7]])
                    + Bhy1 * (Bhx0 * W[toffB[8]]  + Blx0 * W[toffB[9]])
                    + Bly1 * (Bhx0 * W[toffB[10]] + Blx0 * W[toffB[11]])
                    + Bhy1 * (Bhx1 * W[toffB[12]] + Blx1 * W[toffB[13]])
                    + Bly1 * (Bhx1 * W[toffB[14]] + Blx1 * W[toffB[15]]);
            }
            float* on = outn + (cbase + k * 8 + warp) * 49;
            on[lane] = accA * 0.25f;
            if (hasB) on[32 + lane] = accB * 0.25f;
            __syncwarp();
        }
    } else {
        // ---- rare oversized window: direct global gather ----
        #pragma unroll 1
        for (int k = 0; k < 8; k++) {
            const int cglob = cbase + k * 8 + warp;
            const float* src = base + (size_t)cglob * HH;
            #pragma unroll 1
            for (int half = 0; half < 2; half++) {
                int bin = half * 32 + lane;
                if (bin >= 49) break;
                int oy = bin / 7, ox = bin - oy * 7;
                float acc = 0.0f;
                #pragma unroll
                for (int sy = 0; sy < 2; sy++) {
                    int j = oy * 2 + sy;
                    float hy = s_hy[j], ly = s_ly[j];
                    int ra = (s_yl[j] + y0) * H, rb = (s_yh[j] + y0) * H;
                    #pragma unroll
                    for (int sx = 0; sx < 2; sx++) {
                        int kk = ox * 2 + sx;
                        float hx = s_hx[kk], lx = s_lx[kk];
                        int xa = s_xl[kk] + x0d, xb = s_xh[kk] + x0d;
                        acc += hy * (hx * __ldg(src + ra + xa) + lx * __ldg(src + ra + xb))
                             + ly * (hx * __ldg(src + rb + xa) + lx * __ldg(src + rb + xb));
                    }
                }
                outn[cglob * 49 + bin] = acc * 0.25f;
            }
        }
    }
}

extern "C" void kernel_launch(void* const* d_in, const int* in_sizes, int n_in,
                              void* d_out, int out_size)
{
    const float* f0 = (const float*)d_in[0];
    const float* f1 = (const float*)d_in[1];
    const float* f2 = (const float*)d_in[2];
    const float* f3 = (const float*)d_in[3];
    const float* boxes = (const float*)d_in[4];
    float* out = (float*)d_out;

    msroi_kernel<<<dim3(512, 4), 256>>>(f0, f1, f2, f3, boxes, out);
}

// round 15
// speedup vs baseline: 1.4818x; 1.0567x over previous
#include <cuda_runtime.h>
#include <cstdint>

// ---------------------------------------------------------------------------
// MultiScaleRoIAlign (torchvision, aligned=False, SR=2) — warp-pair + diet.
// grid=(512 rois, 4 slices of 64 ch), block=256 (4 warp-pairs), 3 blocks/SM.
// Pair p owns channels {cbase + k*4 + p}, k=0..15; cp.async8 3-buffer ring,
// prefetch 2, staged by the 64-lane pair pool with pointer-increment loops.
// One bin per lane (warp0: 0-24, warp1: 25-48); 16 precombined tap offsets
// per lane. Pair-scoped named barriers only.
// Oversized windows (hr*rs2 > 512 float2) -> direct-global fallback.
// ---------------------------------------------------------------------------

#define WS2 512   // float2 slots per window buffer

__device__ __forceinline__ void cp_a8(uint32_t dst, const void* src)
{
    asm volatile("cp.async.ca.shared.global [%0], [%1], 8;"
                 :: "r"(dst), "l"(src) : "memory");
}
__device__ __forceinline__ void cp_a4(uint32_t dst, const void* src)
{
    asm volatile("cp.async.ca.shared.global [%0], [%1], 4;"
                 :: "r"(dst), "l"(src) : "memory");
}
#define CP_COMMIT()  asm volatile("cp.async.commit_group;" ::: "memory")
#define CP_WAIT(N)   asm volatile("cp.async.wait_group %0;" :: "n"(N) : "memory")

__global__ void __launch_bounds__(256, 3)
msroi_kernel(const float* __restrict__ f0, const float* __restrict__ f1,
             const float* __restrict__ f2, const float* __restrict__ f3,
             const float* __restrict__ boxes, float* __restrict__ out)
{
    __shared__ float2 win[4][3][WS2];                     // 48 KB
    __shared__ float s_hy[14], s_ly[14], s_hx[14], s_lx[14];
    __shared__ int   s_yl[14], s_yh[14], s_xl[14], s_xh[14];

    const int tid = threadIdx.x;
    const int n = blockIdx.x;

    float4 bx = __ldg(reinterpret_cast<const float4*>(boxes) + n);

    // LevelMapper: floor(4 + log2(sqrt(w*h)/224) + 1e-6), clip [2,5], -2
    float s = sqrtf((bx.z - bx.x) * (bx.w - bx.y));
    int lvl = (int)floorf(4.0f + log2f(s * (1.0f / 224.0f)) + 1e-6f);
    lvl = min(max(lvl, 2), 5) - 2;

    int H; float sc; const float* base;
    switch (lvl) {
        case 0:  H = 200; sc = 0.25f;    base = f0; break;
        case 1:  H = 100; sc = 0.125f;   base = f1; break;
        case 2:  H = 50;  sc = 0.0625f;  base = f2; break;
        default: H = 25;  sc = 0.03125f; base = f3; break;
    }
    const int HH = H * H;
    base += (size_t)(n >> 8) * 256 * HH;

    float x1s = bx.x * sc, y1s = bx.y * sc;
    float binw = fmaxf(bx.z * sc - x1s, 1.0f) * (1.0f / 7.0f);
    float binh = fmaxf(bx.w * sc - y1s, 1.0f) * (1.0f / 7.0f);
    float fH = (float)H;

    // window bounds
    int y0  = min((int)fmaxf(y1s + 0.25f * binh, 0.0f), H - 1);
    int x0  = min((int)fmaxf(x1s + 0.25f * binw, 0.0f), H - 1);
    int y1m = min((int)fmaxf(fminf(y1s + 6.75f * binh, fH - 1.0f), 0.0f) + 1, H - 1);
    int x1m = min((int)fmaxf(fminf(x1s + 6.75f * binw, fH - 1.0f), 0.0f) + 1, H - 1);
    const int hr  = y1m - y0 + 1;
    const int x0d = x0 & ~1;                   // float2-aligned window start
    const int wc2 = (x1m >> 1) - (x0d >> 1) + 1;
    const int rs2 = wc2 | 1;                   // odd float2 row stride
    const int rsF = rs2 * 2;                   // float row stride

    // per-sample bilinear params (14 y, 14 x), window-relative indices
    if (tid < 28) {
        bool isY = tid < 14;
        int j = isY ? tid : tid - 14;
        float o = (float)(j >> 1) + 0.25f + 0.5f * (float)(j & 1);
        float v = isY ? (y1s + o * binh) : (x1s + o * binw);
        bool valid = (v > -1.0f) && (v < fH);
        float vc = fmaxf(v, 0.0f);
        int lo = min((int)vc, H - 1);
        int hi = min(lo + 1, H - 1);
        float l = (lo >= H - 1) ? 0.0f : (vc - (float)lo);
        float h = 1.0f - l;
        if (!valid) { l = 0.0f; h = 0.0f; lo = isY ? y0 : x0d; hi = lo; }
        if (isY) { s_yl[j] = lo - y0;  s_yh[j] = hi - y0;  s_ly[j] = l; s_hy[j] = h; }
        else     { s_xl[j] = lo - x0d; s_xh[j] = hi - x0d; s_lx[j] = l; s_hx[j] = h; }
    }
    __syncthreads();                           // only block barrier

    const int warp = tid >> 5, lane = tid & 31;
    const int pair = warp >> 1, wsub = warp & 1;
    const int q = wsub * 32 + lane;            // 0..63 within pair
    const int cbase = blockIdx.y * 64;

    // one bin per lane: warp0 -> bins 0-24, warp1 -> bins 25-48
    const int binRaw = wsub ? (25 + lane) : lane;
    const bool act = lane < (25 - wsub);
    const int bin = min(binRaw, 48);

    // 16 precombined float-element tap offsets + 8 weights
    int toff[16];
    float hy0, ly0, hy1, ly1, hx0, lx0, hx1, lx1;
    {
        int oy = bin / 7, ox = bin - oy * 7;
        int j0 = oy * 2, j1 = j0 + 1, k0 = ox * 2, k1 = k0 + 1;
        int R0 = s_yl[j0] * rsF, R1 = s_yh[j0] * rsF;
        int R2 = s_yl[j1] * rsF, R3 = s_yh[j1] * rsF;
        int C0 = s_xl[k0], C1 = s_xh[k0], C2 = s_xl[k1], C3 = s_xh[k1];
        toff[0]=R0+C0;  toff[1]=R0+C1;  toff[2]=R1+C0;  toff[3]=R1+C1;
        toff[4]=R0+C2;  toff[5]=R0+C3;  toff[6]=R1+C2;  toff[7]=R1+C3;
        toff[8]=R2+C0;  toff[9]=R2+C1;  toff[10]=R3+C0; toff[11]=R3+C1;
        toff[12]=R2+C2; toff[13]=R2+C3; toff[14]=R3+C2; toff[15]=R3+C3;
        hy0=s_hy[j0]; ly0=s_ly[j0]; hy1=s_hy[j1]; ly1=s_ly[j1];
        hx0=s_hx[k0]; lx0=s_lx[k0]; hx1=s_hx[k1]; lx1=s_lx[k1];
    }

    const bool fits = (hr * rs2) <= WS2;       // uniform per block
    const bool h25 = (H == 25);
    const int H2 = H >> 1;
    const int xlim = x1m - x0d;

    // staging geometry: 64-lane pool covers wp2 x-positions x (64/wp2) rows
    const int wide = h25 ? (xlim + 1) : wc2;   // elements per row (f32 / f2)
    int wp2 = 1;
    while (wp2 < wide && wp2 < 64) wp2 <<= 1;
    const int shift = __popc(wp2 - 1);
    const int rpw = 64 >> shift;               // rows per pool step
    const int lxe = q & (wp2 - 1);
    const int lr0 = q >> shift;

    float* outn = out + (size_t)n * 12544;
    const int barid = pair + 1;

    if (fits) {
        const int gstep2 = rpw * H2;           // float2 step (!h25)
        const int sstep2 = rpw * rs2 * 8;      // smem byte step (!h25)
        const int gstepF = rpw * H;            // float step (h25)
        const int sstepF = rpw * rsF * 4;      // smem byte step (h25)

        auto stage = [&](int bf, int k) {
            const int cglob = cbase + k * 4 + pair;
            uint32_t wb = (uint32_t)__cvta_generic_to_shared(&win[pair][bf][0]);
            if (!h25) {
                const float2* g = reinterpret_cast<const float2*>(base)
                                + (size_t)cglob * (HH >> 1) + y0 * H2 + (x0d >> 1);
                if (wide <= 64) {              // common: one x-pass
                    if (lxe < wc2) {
                        const float2* gp = g + lr0 * H2 + lxe;
                        uint32_t sa = wb + (uint32_t)(lr0 * rs2 + lxe) * 8u;
                        for (int r = lr0; r < hr; r += rpw) {
                            cp_a8(sa, gp);
                            gp += gstep2; sa += (uint32_t)sstep2;
                        }
                    }
                } else {                       // rare extra-wide window
                    for (int cx0 = 0; cx0 < wc2; cx0 += wp2) {
                        int xx = cx0 + lxe;
                        if (xx >= wc2) break;
                        const float2* gp = g + lr0 * H2 + xx;
                        uint32_t sa = wb + (uint32_t)(lr0 * rs2 + xx) * 8u;
                        for (int r = lr0; r < hr; r += rpw) {
                            cp_a8(sa, gp);
                            gp += gstep2; sa += (uint32_t)sstep2;
                        }
                    }
                }
            } else {                           // H=25: wide<=25, one x-pass
                const float* g = base + (size_t)cglob * HH + y0 * H + x0d;
                if (lxe <= xlim) {
                    const float* gp = g + lr0 * H + lxe;
                    uint32_t sa = wb + (uint32_t)(lr0 * rsF + lxe) * 4u;
                    for (int r = lr0; r < hr; r += rpw) {
                        cp_a4(sa, gp);
                        gp += gstepF; sa += (uint32_t)sstepF;
                    }
                }
            }
        };

        stage(0, 0); CP_COMMIT();
        stage(1, 1); CP_COMMIT();

        #pragma unroll 1
        for (int k = 0; k < 16; k++) {
            int bf = k % 3;
            if (k + 2 < 16) {
                stage((k + 2) % 3, k + 2);     // buf freed by barrier B below
                CP_COMMIT();
                CP_WAIT(2);
            } else if (k + 1 < 16) {
                CP_WAIT(1);
            } else {
                CP_WAIT(0);
            }
            // barrier A: partner warp's copies for buf k%3 landed too
            asm volatile("bar.sync %0, 64;" :: "r"(barid) : "memory");

            const float* W = reinterpret_cast<const float*>(win[pair][bf]);
            float acc =
                  hy0 * (hx0 * W[toff[0]]  + lx0 * W[toff[1]])
                + ly0 * (hx0 * W[toff[2]]  + lx0 * W[toff[3]])
                + hy0 * (hx1 * W[toff[4]]  + lx1 * W[toff[5]])
                + ly0 * (hx1 * W[toff[6]]  + lx1 * W[toff[7]])
                + hy1 * (hx0 * W[toff[8]]  + lx0 * W[toff[9]])
                + ly1 * (hx0 * W[toff[10]] + lx0 * W[toff[11]])
                + hy1 * (hx1 * W[toff[12]] + lx1 * W[toff[13]])
                + ly1 * (hx1 * W[toff[14]] + lx1 * W[toff[15]]);
            if (act)
                outn[(cbase + k * 4 + pair) * 49 + binRaw] = acc * 0.25f;

            // barrier B: both warps done reading buf before it is restaged
            asm volatile("bar.sync %0, 64;" :: "r"(barid) : "memory");
        }
    } else {
        // ---- rare oversized window: direct global gather ----
        #pragma unroll 1
        for (int k = 0; k < 16; k++) {
            const int cglob = cbase + k * 4 + pair;
            const float* src = base + (size_t)cglob * HH;
            int oy = bin / 7, ox = bin - oy * 7;
            float acc = 0.0f;
            #pragma unroll
            for (int sy = 0; sy < 2; sy++) {
                int j = oy * 2 + sy;
                float hy = s_hy[j], ly = s_ly[j];
                int ra = (s_yl[j] + y0) * H, rb = (s_yh[j] + y0) * H;
                #pragma unroll
                for (int sx = 0; sx < 2; sx++) {
                    int kk = ox * 2 + sx;
                    float hx = s_hx[kk], lx = s_lx[kk];
                    int xa = s_xl[kk] + x0d, xb = s_xh[kk] + x0d;
                    acc += hy * (hx * __ldg(src + ra + xa) + lx * __ldg(src + ra + xb))
                         + ly * (hx * __ldg(src + rb + xa) + lx * __ldg(src + rb + xb));
                }
            }
            if (act)
                outn[cglob * 49 + binRaw] = acc * 0.25f;
        }
    }
}

extern "C" void kernel_launch(void* const* d_in, const int* in_sizes, int n_in,
                              void* d_out, int out_size)
{
    const float* f0 = (const float*)d_in[0];
    const float* f1 = (const float*)d_in[1];
    const float* f2 = (const float*)d_in[2];
    const float* f3 = (const float*)d_in[3];
    const float* boxes = (const float*)d_in[4];
    float* out = (float*)d_out;

    msroi_kernel<<<dim3(512, 4), 256>>>(f0, f1, f2, f3, boxes, out);
}